// round 4
// baseline (speedup 1.0000x reference)
#include <cuda_runtime.h>
#include <cstdint>

// LearnableFiltration via mma.sync tf32 (sm_103 family target: no tcgen05).
// out[b,i,j] = softplus( relu( relu(H1) @ W2 + b2 ) @ W3 + b3 )
// H1[j,h] = wi*W1[0,h] + wj*W1[1,h] + d_ij*W1[2,h] + b1[h];  B=4,N=1024,H=32.
//
// R4: -cvt on A (HW tf32 truncation), b2 folded into first MMA's C operand,
// flat 32-bit addressing (elem offset = t*16+g), per-tile ai precompute,
// 4 blocks/SM (GRID=592), streaming ld/st.

#define NB    4
#define NN    1024
#define NH    32
#define TPB   128
#define GRID  592                        // 4 blocks/SM * 148 SMs
#define NWT   (NB * NN * (NN / 16))      // 262144 warp-tiles of 16 j's

static __device__ __forceinline__ uint32_t to_tf32(float x) {
    uint32_t r;
    asm("cvt.rna.tf32.f32 %0, %1;" : "=r"(r) : "f"(x));
    return r;
}

// D = A*B + acc (in-place accumulate)
static __device__ __forceinline__ void mma_acc(float* d, const uint32_t* a,
                                               const uint32_t* b) {
    asm volatile(
        "mma.sync.aligned.m16n8k8.row.col.f32.tf32.tf32.f32 "
        "{%0,%1,%2,%3}, {%4,%5,%6,%7}, {%8,%9}, {%0,%1,%2,%3};"
        : "+f"(d[0]), "+f"(d[1]), "+f"(d[2]), "+f"(d[3])
        : "r"(a[0]), "r"(a[1]), "r"(a[2]), "r"(a[3]), "r"(b[0]), "r"(b[1]));
}
// D = A*B + {c0,c1,c0,c1}  (bias init: writes D fresh, no zero/copy init)
static __device__ __forceinline__ void mma_bias(float* d, const uint32_t* a,
                                                const uint32_t* b,
                                                float c0, float c1) {
    asm volatile(
        "mma.sync.aligned.m16n8k8.row.col.f32.tf32.tf32.f32 "
        "{%0,%1,%2,%3}, {%4,%5,%6,%7}, {%8,%9}, {%10,%11,%10,%11};"
        : "=f"(d[0]), "=f"(d[1]), "=f"(d[2]), "=f"(d[3])
        : "r"(a[0]), "r"(a[1]), "r"(a[2]), "r"(a[3]), "r"(b[0]), "r"(b[1]),
          "f"(c0), "f"(c1));
}

static __device__ __forceinline__ float ldg_cs(const float* p) {
    float v;
    asm volatile("ld.global.cs.f32 %0, [%1];" : "=f"(v) : "l"(p));
    return v;
}
static __device__ __forceinline__ void stg_cs(float* p, float v) {
    asm volatile("st.global.cs.f32 [%0], %1;" :: "l"(p), "f"(v));
}

__global__ void __launch_bounds__(TPB, 4)
lf_mma4_kernel(const float* __restrict__ weights,
               const float* __restrict__ distances,
               const float* __restrict__ W1,
               const float* __restrict__ b1,
               const float* __restrict__ W2,
               const float* __restrict__ b2,
               const float* __restrict__ W3,
               const float* __restrict__ b3,
               float* __restrict__ out)
{
    __shared__ float  sW[NB * NN];    // all weights (16 KB)
    __shared__ float2 sW1xw[NH];      // {W1[0,h], b1[h]}
    __shared__ float2 sW1yz[NH];      // {W1[1,h], W1[2,h]}
    __shared__ float2 sBW[NH];        // {b2[k], W3[k]}
    __shared__ float  sW2[NH * NH];   // W2[h][n] row-major

    const int tid  = threadIdx.x;
    const int wid  = tid >> 5;
    const int lane = tid & 31;
    const int q    = lane & 3;
    const int g    = lane >> 2;

    for (int x = tid; x < (NB * NN) / 4; x += TPB)
        ((float4*)sW)[x] = ((const float4*)weights)[x];
    for (int x = tid; x < (NH * NH) / 4; x += TPB)
        ((float4*)sW2)[x] = ((const float4*)W2)[x];
    if (tid < NH) {
        sW1xw[tid] = make_float2(W1[tid], b1[tid]);
        sW1yz[tid] = make_float2(W1[NH + tid], W1[2 * NH + tid]);
        sBW[tid]   = make_float2(b2[tid], W3[tid]);
    }
    __syncthreads();

    // ---- loop-invariant register state ----
    // B fragments: bf[kt][nt] = {W2[8kt+q][8nt+g], W2[8kt+q+4][8nt+g]} (tf32)
    uint32_t bf[4][4][2];
#pragma unroll
    for (int kt = 0; kt < 4; kt++)
#pragma unroll
        for (int nt = 0; nt < 4; nt++) {
            bf[kt][nt][0] = to_tf32(sW2[(kt * 8 + q) * NH + nt * 8 + g]);
            bf[kt][nt][1] = to_tf32(sW2[(kt * 8 + q + 4) * NH + nt * 8 + g]);
        }
    // W1[1],W1[2] at this thread's k-columns (h = q + {0,4} + 8kt)
    float2 w1yz[8];
#pragma unroll
    for (int kt = 0; kt < 4; kt++) {
        w1yz[2 * kt]     = sW1yz[8 * kt + q];
        w1yz[2 * kt + 1] = sW1yz[8 * kt + q + 4];
    }
    // (b2, W3) at this thread's D columns: n = 8nt + 2q + {0,1}
    float2 bw[8];
#pragma unroll
    for (int nt = 0; nt < 4; nt++) {
        bw[2 * nt]     = sBW[8 * nt + 2 * q];
        bw[2 * nt + 1] = sBW[8 * nt + 2 * q + 1];
    }
    const float b3v = b3[0];
    // smem pointers for per-tile ai loads (loop-invariant addresses)
    const float2* aixw0 = &sW1xw[q];       // +8kt, and +4 for second
    const float2* aixw1 = &sW1xw[q + 4];

    const int gw     = blockIdx.x * 4 + wid;
    const int stride = GRID * 4;

    // prefetch first tile's distances (flat elem offset = t*16 + g)
    float d0 = 0.f, d1 = 0.f;
    if (gw < NWT) {
        const unsigned off = ((unsigned)gw << 4) + g;
        d0 = ldg_cs(distances + off);
        d1 = ldg_cs(distances + off + 8);
    }

    for (int t = gw; t < NWT; t += stride) {
        const unsigned off = ((unsigned)t << 4) + g;     // flat b,i,j offset

        // wi / wj from smem; ai[h] = wi*W1[0,h] + b1[h]
        const float wi = sW[t >> 6];
        const unsigned jbase = ((unsigned)(t >> 16) << 10) + ((t & 63) << 4) + g;
        const float wj0 = sW[jbase];
        const float wj1 = sW[jbase + 8];

        float ai[8];
#pragma unroll
        for (int kt = 0; kt < 4; kt++) {
            const float2 xw0 = aixw0[8 * kt];
            const float2 xw1 = aixw1[8 * kt];
            ai[2 * kt]     = fmaf(xw0.x, wi, xw0.y);
            ai[2 * kt + 1] = fmaf(xw1.x, wi, xw1.y);
        }

        // ---- A fragments: rows {g,g+8}, cols q+{0,4}+8kt; raw-bit tf32 ----
        uint32_t af[4][4];
#pragma unroll
        for (int kt = 0; kt < 4; kt++) {
            const float2 yzA = w1yz[2 * kt];
            const float2 yzB = w1yz[2 * kt + 1];
            af[kt][0] = __float_as_uint(fmaxf(fmaf(yzA.y, d0, fmaf(yzA.x, wj0, ai[2*kt])), 0.f));
            af[kt][1] = __float_as_uint(fmaxf(fmaf(yzA.y, d1, fmaf(yzA.x, wj1, ai[2*kt])), 0.f));
            af[kt][2] = __float_as_uint(fmaxf(fmaf(yzB.y, d0, fmaf(yzB.x, wj0, ai[2*kt+1])), 0.f));
            af[kt][3] = __float_as_uint(fmaxf(fmaf(yzB.y, d1, fmaf(yzB.x, wj1, ai[2*kt+1])), 0.f));
        }

        // prefetch next tile
        const int tn = t + stride;
        float d0n = 0.f, d1n = 0.f;
        if (tn < NWT) {
            const unsigned offn = ((unsigned)tn << 4) + g;
            d0n = ldg_cs(distances + offn);
            d1n = ldg_cs(distances + offn + 8);
        }

        // ---- 16 HMMAs; first per nt carries b2 bias as C ----
        float acc[4][4];
#pragma unroll
        for (int nt = 0; nt < 4; nt++)
            mma_bias(acc[nt], af[0], bf[0][nt], bw[2*nt].x, bw[2*nt+1].x);
#pragma unroll
        for (int kt = 1; kt < 4; kt++)
#pragma unroll
            for (int nt = 0; nt < 4; nt++)
                mma_acc(acc[nt], af[kt], bf[kt][nt]);

        // ---- epilogue: relu . W3, quad reduce, softplus ----
        float s0 = 0.f, s1 = 0.f;
#pragma unroll
        for (int nt = 0; nt < 4; nt++) {
            const float w30 = bw[2 * nt].y;
            const float w31 = bw[2 * nt + 1].y;
            s0 = fmaf(fmaxf(acc[nt][0], 0.f), w30, s0);
            s0 = fmaf(fmaxf(acc[nt][1], 0.f), w31, s0);
            s1 = fmaf(fmaxf(acc[nt][2], 0.f), w30, s1);
            s1 = fmaf(fmaxf(acc[nt][3], 0.f), w31, s1);
        }
        s0 += __shfl_xor_sync(0xffffffffu, s0, 1);
        s0 += __shfl_xor_sync(0xffffffffu, s0, 2);
        s1 += __shfl_xor_sync(0xffffffffu, s1, 1);
        s1 += __shfl_xor_sync(0xffffffffu, s1, 2);

        if (q == 0) {
            const float x0 = s0 + b3v;
            const float x1 = s1 + b3v;
            stg_cs(out + off,     fmaxf(x0, 0.f) + log1pf(expf(-fabsf(x0))));
            stg_cs(out + off + 8, fmaxf(x1, 0.f) + log1pf(expf(-fabsf(x1))));
        }

        d0 = d0n;
        d1 = d1n;
    }
}

extern "C" void kernel_launch(void* const* d_in, const int* in_sizes, int n_in,
                              void* d_out, int out_size)
{
    const float* weights   = (const float*)d_in[0];
    const float* distances = (const float*)d_in[1];
    const float* W1        = (const float*)d_in[2];
    const float* b1        = (const float*)d_in[3];
    const float* W2        = (const float*)d_in[4];
    const float* b2        = (const float*)d_in[5];
    const float* W3        = (const float*)d_in[6];
    const float* b3        = (const float*)d_in[7];
    float* out             = (float*)d_out;

    lf_mma4_kernel<<<GRID, TPB>>>(weights, distances, W1, b1, W2, b2, W3, b3, out);
}

// round 5
// speedup vs baseline: 2.0200x; 2.0200x over previous
#include <cuda_runtime.h>
#include <cstdint>

// LearnableFiltration via mma.sync tf32 (sm_103 family target: no tcgen05).
// out[b,i,j] = softplus( relu( relu(H1) @ W2 + b2 ) @ W3 + b3 )
// H1[j,h] = wi*W1[0,h] + wj*W1[1,h] + d_ij*W1[2,h] + b1[h];  B=4,N=1024,H=32.
//
// R5 = R3 structure (444 blocks, hoisted W1 regs, no reg cap) +
//   raw-bit tf32 A-frags (no cvt), b2 folded into MMA C operand,
//   MUFU-approx softplus, __ldcs/__stcs.

#define NB    4
#define NN    1024
#define NH    32
#define TPB   128                        // 4 warps / block
#define GRID  444                        // persistent; ~3 blocks/SM
#define NWT   (NB * NN * (NN / 16))      // 262144 warp-tiles of 16 j's

static __device__ __forceinline__ uint32_t to_tf32(float x) {
    uint32_t r;
    asm("cvt.rna.tf32.f32 %0, %1;" : "=r"(r) : "f"(x));
    return r;
}

// D += A*B (in-place accumulate)
static __device__ __forceinline__ void mma_acc(float* d, const uint32_t* a,
                                               const uint32_t* b) {
    asm volatile(
        "mma.sync.aligned.m16n8k8.row.col.f32.tf32.tf32.f32 "
        "{%0,%1,%2,%3}, {%4,%5,%6,%7}, {%8,%9}, {%0,%1,%2,%3};"
        : "+f"(d[0]), "+f"(d[1]), "+f"(d[2]), "+f"(d[3])
        : "r"(a[0]), "r"(a[1]), "r"(a[2]), "r"(a[3]), "r"(b[0]), "r"(b[1]));
}
// D = A*B + {c0,c1,c0,c1}  (bias init: writes D fresh)
static __device__ __forceinline__ void mma_bias(float* d, const uint32_t* a,
                                                const uint32_t* b,
                                                float c0, float c1) {
    asm volatile(
        "mma.sync.aligned.m16n8k8.row.col.f32.tf32.tf32.f32 "
        "{%0,%1,%2,%3}, {%4,%5,%6,%7}, {%8,%9}, {%10,%11,%10,%11};"
        : "=f"(d[0]), "=f"(d[1]), "=f"(d[2]), "=f"(d[3])
        : "r"(a[0]), "r"(a[1]), "r"(a[2]), "r"(a[3]), "r"(b[0]), "r"(b[1]),
          "f"(c0), "f"(c1));
}

// softplus(x) = max(x,0) + ln2 * lg2(1 + 2^(-|x|*log2e)), MUFU approx
static __device__ __forceinline__ float softplus_fast(float x) {
    float t, l;
    const float nax = -fabsf(x) * 1.442695041f;
    asm("ex2.approx.f32 %0, %1;" : "=f"(t) : "f"(nax));
    asm("lg2.approx.f32 %0, %1;" : "=f"(l) : "f"(t + 1.0f));
    return fmaxf(x, 0.0f) + 0.693147181f * l;
}

__global__ void __launch_bounds__(TPB)
lf_mma5_kernel(const float* __restrict__ weights,
               const float* __restrict__ distances,
               const float* __restrict__ W1,
               const float* __restrict__ b1,
               const float* __restrict__ W2,
               const float* __restrict__ b2,
               const float* __restrict__ W3,
               const float* __restrict__ b3,
               float* __restrict__ out)
{
    __shared__ float  sW[NB * NN];    // all weights (16 KB)
    __shared__ float4 sW1[NH];        // {W1[0,h], W1[1,h], W1[2,h], b1[h]}
    __shared__ float2 sBW[NH];        // {b2[k], W3[k]}
    __shared__ float  sW2[NH * NH];   // W2[h][n] row-major

    const int tid  = threadIdx.x;
    const int wid  = tid >> 5;
    const int lane = tid & 31;
    const int q    = lane & 3;        // k / col position in quad
    const int g    = lane >> 2;       // row position

    for (int x = tid; x < (NB * NN) / 4; x += TPB)
        ((float4*)sW)[x] = ((const float4*)weights)[x];
    for (int x = tid; x < (NH * NH) / 4; x += TPB)
        ((float4*)sW2)[x] = ((const float4*)W2)[x];
    if (tid < NH) {
        sW1[tid] = make_float4(W1[tid], W1[NH + tid], W1[2 * NH + tid], b1[tid]);
        sBW[tid] = make_float2(b2[tid], W3[tid]);
    }
    __syncthreads();

    // ---- loop-invariant register state ----
    uint32_t bf[4][4][2];             // W2^T fragments (tf32)
#pragma unroll
    for (int kt = 0; kt < 4; kt++)
#pragma unroll
        for (int nt = 0; nt < 4; nt++) {
            bf[kt][nt][0] = to_tf32(sW2[(kt * 8 + q) * NH + nt * 8 + g]);
            bf[kt][nt][1] = to_tf32(sW2[(kt * 8 + q + 4) * NH + nt * 8 + g]);
        }
    float4 w1c[8];                    // W1 cols h = q + {0,4} + 8kt
#pragma unroll
    for (int kt = 0; kt < 4; kt++) {
        w1c[2 * kt]     = sW1[8 * kt + q];
        w1c[2 * kt + 1] = sW1[8 * kt + q + 4];
    }
    float2 bw[8];                     // {b2, W3} at n = 8nt + 2q + {0,1}
#pragma unroll
    for (int nt = 0; nt < 4; nt++) {
        bw[2 * nt]     = sBW[8 * nt + 2 * q];
        bw[2 * nt + 1] = sBW[8 * nt + 2 * q + 1];
    }
    const float b3v = b3[0];

    const int gw     = blockIdx.x * 4 + wid;
    const int stride = GRID * 4;

    // prefetch first tile's distances (flat elem offset = t*16 + g)
    float d0 = 0.f, d1 = 0.f;
    if (gw < NWT) {
        const unsigned off = ((unsigned)gw << 4) + g;
        d0 = __ldcs(distances + off);
        d1 = __ldcs(distances + off + 8);
    }

    for (int t = gw; t < NWT; t += stride) {
        const unsigned off = ((unsigned)t << 4) + g;

        const float wi = sW[t >> 6];
        const unsigned jbase = ((unsigned)(t >> 16) << 10) + ((t & 63) << 4) + g;
        const float wj0 = sW[jbase];
        const float wj1 = sW[jbase + 8];

        // ---- A fragments: rows {g,g+8}, cols q+{0,4}+8kt; raw-bit tf32 ----
        uint32_t af[4][4];
#pragma unroll
        for (int kt = 0; kt < 4; kt++) {
            const float4 cA = w1c[2 * kt];
            const float4 cB = w1c[2 * kt + 1];
            const float aiA = fmaf(cA.x, wi, cA.w);
            const float aiB = fmaf(cB.x, wi, cB.w);
            af[kt][0] = __float_as_uint(fmaxf(fmaf(cA.z, d0, fmaf(cA.y, wj0, aiA)), 0.f));
            af[kt][1] = __float_as_uint(fmaxf(fmaf(cA.z, d1, fmaf(cA.y, wj1, aiA)), 0.f));
            af[kt][2] = __float_as_uint(fmaxf(fmaf(cB.z, d0, fmaf(cB.y, wj0, aiB)), 0.f));
            af[kt][3] = __float_as_uint(fmaxf(fmaf(cB.z, d1, fmaf(cB.y, wj1, aiB)), 0.f));
        }

        // prefetch next tile (hide LDG under MMA + epilogue)
        const int tn = t + stride;
        float d0n = 0.f, d1n = 0.f;
        if (tn < NWT) {
            const unsigned offn = ((unsigned)tn << 4) + g;
            d0n = __ldcs(distances + offn);
            d1n = __ldcs(distances + offn + 8);
        }

        // ---- 16 HMMAs; first k-step carries b2 bias as C ----
        float acc[4][4];
#pragma unroll
        for (int nt = 0; nt < 4; nt++)
            mma_bias(acc[nt], af[0], bf[0][nt], bw[2 * nt].x, bw[2 * nt + 1].x);
#pragma unroll
        for (int kt = 1; kt < 4; kt++)
#pragma unroll
            for (int nt = 0; nt < 4; nt++)
                mma_acc(acc[nt], af[kt], bf[kt][nt]);

        // ---- epilogue: relu . W3, quad reduce, softplus ----
        float s0 = 0.f, s1 = 0.f;
#pragma unroll
        for (int nt = 0; nt < 4; nt++) {
            const float w30 = bw[2 * nt].y;
            const float w31 = bw[2 * nt + 1].y;
            s0 = fmaf(fmaxf(acc[nt][0], 0.f), w30, s0);
            s0 = fmaf(fmaxf(acc[nt][1], 0.f), w31, s0);
            s1 = fmaf(fmaxf(acc[nt][2], 0.f), w30, s1);
            s1 = fmaf(fmaxf(acc[nt][3], 0.f), w31, s1);
        }
        s0 += __shfl_xor_sync(0xffffffffu, s0, 1);
        s0 += __shfl_xor_sync(0xffffffffu, s0, 2);
        s1 += __shfl_xor_sync(0xffffffffu, s1, 1);
        s1 += __shfl_xor_sync(0xffffffffu, s1, 2);

        if (q == 0) {
            __stcs(out + off,     softplus_fast(s0 + b3v));
            __stcs(out + off + 8, softplus_fast(s1 + b3v));
        }

        d0 = d0n;
        d1 = d1n;
    }
}

extern "C" void kernel_launch(void* const* d_in, const int* in_sizes, int n_in,
                              void* d_out, int out_size)
{
    const float* weights   = (const float*)d_in[0];
    const float* distances = (const float*)d_in[1];
    const float* W1        = (const float*)d_in[2];
    const float* b1        = (const float*)d_in[3];
    const float* W2        = (const float*)d_in[4];
    const float* b2        = (const float*)d_in[5];
    const float* W3        = (const float*)d_in[6];
    const float* b3        = (const float*)d_in[7];
    float* out             = (float*)d_out;

    lf_mma5_kernel<<<GRID, TPB>>>(weights, distances, W1, b1, W2, b2, W3, b3, out);
}